// round 1
// baseline (speedup 1.0000x reference)
#include <cuda_runtime.h>
#include <cuda_bf16.h>

// Problem constants
#define BDIM  4096
#define TDIM  32
#define KDIM  16
#define DDIM  512
#define HDIM  1024   // = 2*D
#define H2DIM 2048   // = 2*H

// Scratch (device globals: allocation-free rule)
__device__ float g_hat_buf[BDIM * DDIM];    // (B, D)
__device__ float E1_buf[BDIM * HDIM];       // g_hat @ W1[:512] + b1
__device__ float e_buf[BDIM * TDIM];        // attention scores
__device__ float xhat_buf[BDIM * DDIM];     // attention-pooled x
__device__ float E2_buf[BDIM * H2DIM];      // x_hat @ M1[:512] + c1

// ---------------------------------------------------------------------------
// K1: g_hat = mean_k G  (B*D threads)
// ---------------------------------------------------------------------------
__global__ void gmean_kernel(const float* __restrict__ G, float* __restrict__ out) {
    int idx = blockIdx.x * blockDim.x + threadIdx.x;     // over B*D
    int b = idx / DDIM;
    int d = idx - b * DDIM;
    const float* g = G + (size_t)b * KDIM * DDIM + d;
    float s = 0.f;
#pragma unroll
    for (int k = 0; k < KDIM; k++) s += g[k * DDIM];
    out[idx] = s * (1.0f / KDIM);
}

// ---------------------------------------------------------------------------
// K2/K5: C(M,N) = A(M,512) @ W(512,N) + bias(N).   BM=BN=64, BK=16, 256 thr.
// ---------------------------------------------------------------------------
__global__ void __launch_bounds__(256) sgemm_bias_kernel(
    const float* __restrict__ A, int lda,
    const float* __restrict__ W, int ldw,
    const float* __restrict__ bias,
    float* __restrict__ C, int N, int Kd)
{
    const int BM = 64, BN = 64, BK = 16;
    __shared__ float As[BM][BK + 1];
    __shared__ float Ws[BK][BN];
    int tx = threadIdx.x & 15, ty = threadIdx.x >> 4;
    int rb = blockIdx.y * BM;
    int cb = blockIdx.x * BN;

    int la_m = threadIdx.x >> 2;
    int la_q = (threadIdx.x & 3) << 2;
    int lw_k = threadIdx.x >> 4;
    int lw_q = (threadIdx.x & 15) << 2;

    float acc[4][4] = {};
    for (int k0 = 0; k0 < Kd; k0 += BK) {
        float4 av = *(const float4*)&A[(size_t)(rb + la_m) * lda + k0 + la_q];
        As[la_m][la_q + 0] = av.x; As[la_m][la_q + 1] = av.y;
        As[la_m][la_q + 2] = av.z; As[la_m][la_q + 3] = av.w;
        *(float4*)&Ws[lw_k][lw_q] =
            *(const float4*)&W[(size_t)(k0 + lw_k) * ldw + cb + lw_q];
        __syncthreads();
#pragma unroll
        for (int k = 0; k < BK; k++) {
            float4 wv = *(const float4*)&Ws[k][tx << 2];
            float a0 = As[ty * 4 + 0][k], a1 = As[ty * 4 + 1][k];
            float a2 = As[ty * 4 + 2][k], a3 = As[ty * 4 + 3][k];
            acc[0][0] += a0 * wv.x; acc[0][1] += a0 * wv.y; acc[0][2] += a0 * wv.z; acc[0][3] += a0 * wv.w;
            acc[1][0] += a1 * wv.x; acc[1][1] += a1 * wv.y; acc[1][2] += a1 * wv.z; acc[1][3] += a1 * wv.w;
            acc[2][0] += a2 * wv.x; acc[2][1] += a2 * wv.y; acc[2][2] += a2 * wv.z; acc[2][3] += a2 * wv.w;
            acc[3][0] += a3 * wv.x; acc[3][1] += a3 * wv.y; acc[3][2] += a3 * wv.z; acc[3][3] += a3 * wv.w;
        }
        __syncthreads();
    }
    float4 bv = *(const float4*)&bias[cb + (tx << 2)];
#pragma unroll
    for (int i = 0; i < 4; i++) {
        int row = rb + ty * 4 + i;
        float4 o;
        o.x = acc[i][0] + bv.x; o.y = acc[i][1] + bv.y;
        o.z = acc[i][2] + bv.z; o.w = acc[i][3] + bv.w;
        *(float4*)&C[(size_t)row * N + cb + (tx << 2)] = o;
    }
}

// ---------------------------------------------------------------------------
// K3/K6: out[row] = sum_n relu( (A@W)[row,n] + Eb[row/RPB, n] ) * wvec[n] (+ sc)
// A: (M,512) row-major; W: (512,N) row-major; loops all N tiles per block.
// ---------------------------------------------------------------------------
template <int ROWS_PER_B>
__global__ void __launch_bounds__(256) fused_reduce_kernel(
    const float* __restrict__ A,
    const float* __restrict__ W,
    const float* __restrict__ Eb,
    const float* __restrict__ wvec,
    const float* __restrict__ addsc,   // nullable device scalar
    float* __restrict__ out,
    int N)
{
    const int BM = 64, BN = 64, BK = 16, KD = DDIM;
    __shared__ float As[BM][BK + 1];
    __shared__ float Ws[BK][BN];
    int tx = threadIdx.x & 15, ty = threadIdx.x >> 4;
    int rb = blockIdx.x * BM;

    int la_m = threadIdx.x >> 2;
    int la_q = (threadIdx.x & 3) << 2;
    int lw_k = threadIdx.x >> 4;
    int lw_q = (threadIdx.x & 15) << 2;

    int brow = (rb + ty * 4) / ROWS_PER_B;   // constant across i=0..3 (aligned)

    float rowsum[4] = {0.f, 0.f, 0.f, 0.f};
    int ntiles = N / BN;
    for (int nt = 0; nt < ntiles; nt++) {
        int cb = nt * BN;
        float acc[4][4] = {};
        for (int k0 = 0; k0 < KD; k0 += BK) {
            float4 av = *(const float4*)&A[(size_t)(rb + la_m) * KD + k0 + la_q];
            As[la_m][la_q + 0] = av.x; As[la_m][la_q + 1] = av.y;
            As[la_m][la_q + 2] = av.z; As[la_m][la_q + 3] = av.w;
            *(float4*)&Ws[lw_k][lw_q] =
                *(const float4*)&W[(size_t)(k0 + lw_k) * N + cb + lw_q];
            __syncthreads();
#pragma unroll
            for (int k = 0; k < BK; k++) {
                float4 wv = *(const float4*)&Ws[k][tx << 2];
                float a0 = As[ty * 4 + 0][k], a1 = As[ty * 4 + 1][k];
                float a2 = As[ty * 4 + 2][k], a3 = As[ty * 4 + 3][k];
                acc[0][0] += a0 * wv.x; acc[0][1] += a0 * wv.y; acc[0][2] += a0 * wv.z; acc[0][3] += a0 * wv.w;
                acc[1][0] += a1 * wv.x; acc[1][1] += a1 * wv.y; acc[1][2] += a1 * wv.z; acc[1][3] += a1 * wv.w;
                acc[2][0] += a2 * wv.x; acc[2][1] += a2 * wv.y; acc[2][2] += a2 * wv.z; acc[2][3] += a2 * wv.w;
                acc[3][0] += a3 * wv.x; acc[3][1] += a3 * wv.y; acc[3][2] += a3 * wv.z; acc[3][3] += a3 * wv.w;
            }
            __syncthreads();
        }
        float4 ebv = *(const float4*)&Eb[(size_t)brow * N + cb + (tx << 2)];
        float4 wv2 = *(const float4*)&wvec[cb + (tx << 2)];
#pragma unroll
        for (int i = 0; i < 4; i++) {
            rowsum[i] += fmaxf(acc[i][0] + ebv.x, 0.f) * wv2.x
                       + fmaxf(acc[i][1] + ebv.y, 0.f) * wv2.y
                       + fmaxf(acc[i][2] + ebv.z, 0.f) * wv2.z
                       + fmaxf(acc[i][3] + ebv.w, 0.f) * wv2.w;
        }
    }
    // reduce across the 16 tx lanes (they sit in one 16-lane half of a warp)
#pragma unroll
    for (int i = 0; i < 4; i++) {
        float s = rowsum[i];
#pragma unroll
        for (int off = 8; off >= 1; off >>= 1)
            s += __shfl_xor_sync(0xffffffffu, s, off, 16);
        if (tx == 0) {
            float addv = addsc ? *addsc : 0.f;
            out[rb + ty * 4 + i] = s + addv;
        }
    }
}

// ---------------------------------------------------------------------------
// K4: per-b softmax over T=32 then x_hat = sum_t alpha_t * X[b,t,:]
// ---------------------------------------------------------------------------
__global__ void softmax_xhat_kernel(const float* __restrict__ e,
                                    const float* __restrict__ X,
                                    float* __restrict__ xhat)
{
    int b = blockIdx.x;
    __shared__ float alpha[TDIM];
    int tid = threadIdx.x;   // 128 threads
    if (tid < 32) {
        float v = e[b * TDIM + tid];
        float m = v;
#pragma unroll
        for (int off = 16; off >= 1; off >>= 1)
            m = fmaxf(m, __shfl_xor_sync(0xffffffffu, m, off));
        float ex = __expf(v - m);
        float s = ex;
#pragma unroll
        for (int off = 16; off >= 1; off >>= 1)
            s += __shfl_xor_sync(0xffffffffu, s, off);
        alpha[tid] = ex / s;
    }
    __syncthreads();
    const float* Xb = X + (size_t)b * TDIM * DDIM;
#pragma unroll 1
    for (int d = tid; d < DDIM; d += 128) {
        float s = 0.f;
#pragma unroll
        for (int t = 0; t < TDIM; t++) s += alpha[t] * Xb[t * DDIM + d];
        xhat[(size_t)b * DDIM + d] = s;
    }
}

// ---------------------------------------------------------------------------
extern "C" void kernel_launch(void* const* d_in, const int* in_sizes, int n_in,
                              void* d_out, int out_size)
{
    const float* X  = (const float*)d_in[0];
    const float* G  = (const float*)d_in[1];
    const float* W1 = (const float*)d_in[2];
    const float* b1 = (const float*)d_in[3];
    const float* w2 = (const float*)d_in[4];
    // d_in[5] = b2: softmax shift-invariant, unused
    const float* M1 = (const float*)d_in[6];
    const float* c1 = (const float*)d_in[7];
    const float* m2 = (const float*)d_in[8];
    const float* c2 = (const float*)d_in[9];
    float* out = (float*)d_out;

    float *g_hat, *E1, *ebuf, *xh, *E2;
    cudaGetSymbolAddress((void**)&g_hat, g_hat_buf);
    cudaGetSymbolAddress((void**)&E1,    E1_buf);
    cudaGetSymbolAddress((void**)&ebuf,  e_buf);
    cudaGetSymbolAddress((void**)&xh,    xhat_buf);
    cudaGetSymbolAddress((void**)&E2,    E2_buf);

    // K1: g_hat
    gmean_kernel<<<(BDIM * DDIM) / 256, 256>>>(G, g_hat);

    // K2: E1 = g_hat @ W1[:512] + b1    (4096 x 1024)
    {
        dim3 grid(HDIM / 64, BDIM / 64);
        sgemm_bias_kernel<<<grid, 256>>>(g_hat, DDIM, W1, HDIM, b1, E1, HDIM, DDIM);
    }

    // K3: e[b,t] = sum_h relu( X@W1[512:] + E1 ) * w2   (M = 131072)
    fused_reduce_kernel<TDIM><<<(BDIM * TDIM) / 64, 256>>>(
        X, W1 + (size_t)DDIM * HDIM, E1, w2, nullptr, ebuf, HDIM);

    // K4: softmax over T + x_hat
    softmax_xhat_kernel<<<BDIM, 128>>>(ebuf, X, xh);

    // K5: E2 = x_hat @ M1[:512] + c1    (4096 x 2048)
    {
        dim3 grid(H2DIM / 64, BDIM / 64);
        sgemm_bias_kernel<<<grid, 256>>>(xh, DDIM, M1, H2DIM, c1, E2, H2DIM, DDIM);
    }

    // K6: logits[b,k] = sum_j relu( G@M1[512:] + E2 ) * m2 + c2   (M = 65536)
    fused_reduce_kernel<KDIM><<<(BDIM * KDIM) / 64, 256>>>(
        G, M1 + (size_t)DDIM * H2DIM, E2, m2, c2, out, H2DIM);
}

// round 2
// speedup vs baseline: 1.0008x; 1.0008x over previous
#include <cuda_runtime.h>
#include <cuda_bf16.h>

// Problem constants
#define BDIM  4096
#define TDIM  32
#define KDIM  16
#define DDIM  512
#define HDIM  1024   // = 2*D
#define H2DIM 2048   // = 2*H

// Scratch (device globals: allocation-free rule)
__device__ float g_hat_buf[BDIM * DDIM];    // (B, D)
__device__ float E1_buf[BDIM * HDIM];       // g_hat @ W1[:512] + b1
__device__ float e_buf[BDIM * TDIM];        // attention scores
__device__ float xhat_buf[BDIM * DDIM];     // attention-pooled x
__device__ float E2_buf[BDIM * H2DIM];      // x_hat @ M1[:512] + c1

// ---------------------------------------------------------------------------
// K1: g_hat = mean_k G  (B*D threads)
// ---------------------------------------------------------------------------
__global__ void gmean_kernel(const float* __restrict__ G, float* __restrict__ out) {
    int idx = blockIdx.x * blockDim.x + threadIdx.x;     // over B*D
    int b = idx / DDIM;
    int d = idx - b * DDIM;
    const float* g = G + (size_t)b * KDIM * DDIM + d;
    float s = 0.f;
#pragma unroll
    for (int k = 0; k < KDIM; k++) s += g[k * DDIM];
    out[idx] = s * (1.0f / KDIM);
}

// ---------------------------------------------------------------------------
// K2/K5: C(M,N) = A(M,512) @ W(512,N) + bias(N).   BM=BN=64, BK=16, 256 thr.
// ---------------------------------------------------------------------------
__global__ void __launch_bounds__(256) sgemm_bias_kernel(
    const float* __restrict__ A, int lda,
    const float* __restrict__ W, int ldw,
    const float* __restrict__ bias,
    float* __restrict__ C, int N, int Kd)
{
    const int BM = 64, BN = 64, BK = 16;
    __shared__ float As[BM][BK + 1];
    __shared__ float Ws[BK][BN];
    int tx = threadIdx.x & 15, ty = threadIdx.x >> 4;
    int rb = blockIdx.y * BM;
    int cb = blockIdx.x * BN;

    int la_m = threadIdx.x >> 2;
    int la_q = (threadIdx.x & 3) << 2;
    int lw_k = threadIdx.x >> 4;
    int lw_q = (threadIdx.x & 15) << 2;

    float acc[4][4] = {};
    for (int k0 = 0; k0 < Kd; k0 += BK) {
        float4 av = *(const float4*)&A[(size_t)(rb + la_m) * lda + k0 + la_q];
        As[la_m][la_q + 0] = av.x; As[la_m][la_q + 1] = av.y;
        As[la_m][la_q + 2] = av.z; As[la_m][la_q + 3] = av.w;
        *(float4*)&Ws[lw_k][lw_q] =
            *(const float4*)&W[(size_t)(k0 + lw_k) * ldw + cb + lw_q];
        __syncthreads();
#pragma unroll
        for (int k = 0; k < BK; k++) {
            float4 wv = *(const float4*)&Ws[k][tx << 2];
            float a0 = As[ty * 4 + 0][k], a1 = As[ty * 4 + 1][k];
            float a2 = As[ty * 4 + 2][k], a3 = As[ty * 4 + 3][k];
            acc[0][0] += a0 * wv.x; acc[0][1] += a0 * wv.y; acc[0][2] += a0 * wv.z; acc[0][3] += a0 * wv.w;
            acc[1][0] += a1 * wv.x; acc[1][1] += a1 * wv.y; acc[1][2] += a1 * wv.z; acc[1][3] += a1 * wv.w;
            acc[2][0] += a2 * wv.x; acc[2][1] += a2 * wv.y; acc[2][2] += a2 * wv.z; acc[2][3] += a2 * wv.w;
            acc[3][0] += a3 * wv.x; acc[3][1] += a3 * wv.y; acc[3][2] += a3 * wv.z; acc[3][3] += a3 * wv.w;
        }
        __syncthreads();
    }
    float4 bv = *(const float4*)&bias[cb + (tx << 2)];
#pragma unroll
    for (int i = 0; i < 4; i++) {
        int row = rb + ty * 4 + i;
        float4 o;
        o.x = acc[i][0] + bv.x; o.y = acc[i][1] + bv.y;
        o.z = acc[i][2] + bv.z; o.w = acc[i][3] + bv.w;
        *(float4*)&C[(size_t)row * N + cb + (tx << 2)] = o;
    }
}

// ---------------------------------------------------------------------------
// K3/K6: out[row] = sum_n relu( (A@W)[row,n] + Eb[row/RPB, n] ) * wvec[n] (+ sc)
// A: (M,512) row-major; W: (512,N) row-major; loops all N tiles per block.
// ---------------------------------------------------------------------------
template <int ROWS_PER_B>
__global__ void __launch_bounds__(256) fused_reduce_kernel(
    const float* __restrict__ A,
    const float* __restrict__ W,
    const float* __restrict__ Eb,
    const float* __restrict__ wvec,
    const float* __restrict__ addsc,   // nullable device scalar
    float* __restrict__ out,
    int N)
{
    const int BM = 64, BN = 64, BK = 16, KD = DDIM;
    __shared__ float As[BM][BK + 1];
    __shared__ float Ws[BK][BN];
    int tx = threadIdx.x & 15, ty = threadIdx.x >> 4;
    int rb = blockIdx.x * BM;

    int la_m = threadIdx.x >> 2;
    int la_q = (threadIdx.x & 3) << 2;
    int lw_k = threadIdx.x >> 4;
    int lw_q = (threadIdx.x & 15) << 2;

    int brow = (rb + ty * 4) / ROWS_PER_B;   // constant across i=0..3 (aligned)

    float rowsum[4] = {0.f, 0.f, 0.f, 0.f};
    int ntiles = N / BN;
    for (int nt = 0; nt < ntiles; nt++) {
        int cb = nt * BN;
        float acc[4][4] = {};
        for (int k0 = 0; k0 < KD; k0 += BK) {
            float4 av = *(const float4*)&A[(size_t)(rb + la_m) * KD + k0 + la_q];
            As[la_m][la_q + 0] = av.x; As[la_m][la_q + 1] = av.y;
            As[la_m][la_q + 2] = av.z; As[la_m][la_q + 3] = av.w;
            *(float4*)&Ws[lw_k][lw_q] =
                *(const float4*)&W[(size_t)(k0 + lw_k) * N + cb + lw_q];
            __syncthreads();
#pragma unroll
            for (int k = 0; k < BK; k++) {
                float4 wv = *(const float4*)&Ws[k][tx << 2];
                float a0 = As[ty * 4 + 0][k], a1 = As[ty * 4 + 1][k];
                float a2 = As[ty * 4 + 2][k], a3 = As[ty * 4 + 3][k];
                acc[0][0] += a0 * wv.x; acc[0][1] += a0 * wv.y; acc[0][2] += a0 * wv.z; acc[0][3] += a0 * wv.w;
                acc[1][0] += a1 * wv.x; acc[1][1] += a1 * wv.y; acc[1][2] += a1 * wv.z; acc[1][3] += a1 * wv.w;
                acc[2][0] += a2 * wv.x; acc[2][1] += a2 * wv.y; acc[2][2] += a2 * wv.z; acc[2][3] += a2 * wv.w;
                acc[3][0] += a3 * wv.x; acc[3][1] += a3 * wv.y; acc[3][2] += a3 * wv.z; acc[3][3] += a3 * wv.w;
            }
            __syncthreads();
        }
        float4 ebv = *(const float4*)&Eb[(size_t)brow * N + cb + (tx << 2)];
        float4 wv2 = *(const float4*)&wvec[cb + (tx << 2)];
#pragma unroll
        for (int i = 0; i < 4; i++) {
            rowsum[i] += fmaxf(acc[i][0] + ebv.x, 0.f) * wv2.x
                       + fmaxf(acc[i][1] + ebv.y, 0.f) * wv2.y
                       + fmaxf(acc[i][2] + ebv.z, 0.f) * wv2.z
                       + fmaxf(acc[i][3] + ebv.w, 0.f) * wv2.w;
        }
    }
    // reduce across the 16 tx lanes (they sit in one 16-lane half of a warp)
#pragma unroll
    for (int i = 0; i < 4; i++) {
        float s = rowsum[i];
#pragma unroll
        for (int off = 8; off >= 1; off >>= 1)
            s += __shfl_xor_sync(0xffffffffu, s, off, 16);
        if (tx == 0) {
            float addv = addsc ? *addsc : 0.f;
            out[rb + ty * 4 + i] = s + addv;
        }
    }
}

// ---------------------------------------------------------------------------
// K4: per-b softmax over T=32 then x_hat = sum_t alpha_t * X[b,t,:]
// ---------------------------------------------------------------------------
__global__ void softmax_xhat_kernel(const float* __restrict__ e,
                                    const float* __restrict__ X,
                                    float* __restrict__ xhat)
{
    int b = blockIdx.x;
    __shared__ float alpha[TDIM];
    int tid = threadIdx.x;   // 128 threads
    if (tid < 32) {
        float v = e[b * TDIM + tid];
        float m = v;
#pragma unroll
        for (int off = 16; off >= 1; off >>= 1)
            m = fmaxf(m, __shfl_xor_sync(0xffffffffu, m, off));
        float ex = __expf(v - m);
        float s = ex;
#pragma unroll
        for (int off = 16; off >= 1; off >>= 1)
            s += __shfl_xor_sync(0xffffffffu, s, off);
        alpha[tid] = ex / s;
    }
    __syncthreads();
    const float* Xb = X + (size_t)b * TDIM * DDIM;
#pragma unroll 1
    for (int d = tid; d < DDIM; d += 128) {
        float s = 0.f;
#pragma unroll
        for (int t = 0; t < TDIM; t++) s += alpha[t] * Xb[t * DDIM + d];
        xhat[(size_t)b * DDIM + d] = s;
    }
}

// ---------------------------------------------------------------------------
extern "C" void kernel_launch(void* const* d_in, const int* in_sizes, int n_in,
                              void* d_out, int out_size)
{
    const float* X  = (const float*)d_in[0];
    const float* G  = (const float*)d_in[1];
    const float* W1 = (const float*)d_in[2];
    const float* b1 = (const float*)d_in[3];
    const float* w2 = (const float*)d_in[4];
    // d_in[5] = b2: softmax shift-invariant, unused
    const float* M1 = (const float*)d_in[6];
    const float* c1 = (const float*)d_in[7];
    const float* m2 = (const float*)d_in[8];
    const float* c2 = (const float*)d_in[9];
    float* out = (float*)d_out;

    float *g_hat, *E1, *ebuf, *xh, *E2;
    cudaGetSymbolAddress((void**)&g_hat, g_hat_buf);
    cudaGetSymbolAddress((void**)&E1,    E1_buf);
    cudaGetSymbolAddress((void**)&ebuf,  e_buf);
    cudaGetSymbolAddress((void**)&xh,    xhat_buf);
    cudaGetSymbolAddress((void**)&E2,    E2_buf);

    // K1: g_hat
    gmean_kernel<<<(BDIM * DDIM) / 256, 256>>>(G, g_hat);

    // K2: E1 = g_hat @ W1[:512] + b1    (4096 x 1024)
    {
        dim3 grid(HDIM / 64, BDIM / 64);
        sgemm_bias_kernel<<<grid, 256>>>(g_hat, DDIM, W1, HDIM, b1, E1, HDIM, DDIM);
    }

    // K3: e[b,t] = sum_h relu( X@W1[512:] + E1 ) * w2   (M = 131072)
    fused_reduce_kernel<TDIM><<<(BDIM * TDIM) / 64, 256>>>(
        X, W1 + (size_t)DDIM * HDIM, E1, w2, nullptr, ebuf, HDIM);

    // K4: softmax over T + x_hat
    softmax_xhat_kernel<<<BDIM, 128>>>(ebuf, X, xh);

    // K5: E2 = x_hat @ M1[:512] + c1    (4096 x 2048)
    {
        dim3 grid(H2DIM / 64, BDIM / 64);
        sgemm_bias_kernel<<<grid, 256>>>(xh, DDIM, M1, H2DIM, c1, E2, H2DIM, DDIM);
    }

    // K6: logits[b,k] = sum_j relu( G@M1[512:] + E2 ) * m2 + c2   (M = 65536)
    fused_reduce_kernel<KDIM><<<(BDIM * KDIM) / 64, 256>>>(
        G, M1 + (size_t)DDIM * H2DIM, E2, m2, c2, out, H2DIM);
}